// round 2
// baseline (speedup 1.0000x reference)
#include <cuda_runtime.h>

// DenseRadiusGraph: B=16 graphs, N=2048 nodes each, D=3, cutoff=10, K=32.
// Output (float32, concatenated, M = B*N*K = 1048576):
//   [0,   M) : edge_index row (global node id, 0 where invalid)
//   [M,  2M) : edge_index col (global node id, 0 where invalid)
//   [2M, 3M) : edge weight  = ||p_i - p_j||  (0 where invalid)
//   [3M, 4M) : valid flag (1.0 / 0.0)

#define BGRAPHS 16
#define NNODES  2048
#define KNBR    32
#define CAP     64          // max candidates kept; P(Poisson(8.6) >= 64) ~ e^-85
#define TPB     128         // threads per block (1 node per thread)
#define CHUNKS  (NNODES / TPB)   // 16 blocks per graph

__global__ __launch_bounds__(TPB) void dense_radius_graph_kernel(
    const float* __restrict__ pos, float* __restrict__ out)
{
    __shared__ float4 sp[NNODES];   // xyz + |p|^2, 32 KB

    const int b     = blockIdx.x / CHUNKS;   // graph id
    const int chunk = blockIdx.x % CHUNKS;
    const int tid   = threadIdx.x;

    // Stage this graph's positions into shared, with |p|^2 in .w
    const float* gp = pos + (size_t)b * NNODES * 3;
    for (int j = tid; j < NNODES; j += TPB) {
        float x = gp[3 * j + 0];
        float y = gp[3 * j + 1];
        float z = gp[3 * j + 2];
        sp[j] = make_float4(x, y, z, x * x + y * y + z * z);
    }
    __syncthreads();

    const int i = chunk * TPB + tid;         // node index within graph
    const float4 me = sp[i];

    // ---- scan all candidates, collect (dist, j) packed keys ----
    unsigned long long cand[CAP];
    int cnt = 0;

    #pragma unroll 4
    for (int j = 0; j < NNODES; j++) {
        float4 q  = sp[j];                              // warp-uniform -> LDS broadcast
        float dot = me.x * q.x + me.y * q.y + me.z * q.z;
        float d2  = (me.w + q.w) - 2.0f * dot;          // reference GEMM formulation
        // cheap prefilter (generous: covers the rounding band where
        // sqrtf(d2) can still round down to exactly 10.0f)
        if (d2 <= 100.001f && j != i) {
            float dist = sqrtf(fmaxf(d2, 0.0f));        // exact reference mask value
            if (dist <= 10.0f) {
                if (cnt < CAP) {
                    // dist >= 0 -> float bits are order-preserving as uint.
                    // low 32 bits = j -> stable tie-break on lower index,
                    // matching jax.lax.top_k.
                    cand[cnt++] =
                        ((unsigned long long)__float_as_uint(dist) << 32) |
                        (unsigned int)j;
                }
            }
        }
    }

    // ---- insertion sort (ascending dist, then index); cnt ~ 9 on average ----
    for (int a = 1; a < cnt; a++) {
        unsigned long long v = cand[a];
        int c = a - 1;
        while (c >= 0 && cand[c] > v) { cand[c + 1] = cand[c]; c--; }
        cand[c + 1] = v;
    }

    const int m = cnt < KNBR ? cnt : KNBR;

    // ---- write outputs: each thread owns 4 contiguous 128B regions ----
    const size_t M = (size_t)BGRAPHS * NNODES * KNBR;
    const size_t g = (size_t)b * NNODES + i;           // global node id
    float* __restrict__ orow = out + g * KNBR;
    float* __restrict__ ocol = out + M + g * KNBR;
    float* __restrict__ ow   = out + 2 * M + g * KNBR;
    float* __restrict__ oval = out + 3 * M + g * KNBR;

    const float frow = (float)g;
    const int   base = b * NNODES;

    for (int k4 = 0; k4 < KNBR / 4; k4++) {
        float4 r4, c4, w4, v4;
        float* rp = (float*)&r4;
        float* cp = (float*)&c4;
        float* wp = (float*)&w4;
        float* vp = (float*)&v4;
        #pragma unroll
        for (int kk = 0; kk < 4; kk++) {
            int k = k4 * 4 + kk;
            if (k < m) {
                int j = (int)(cand[k] & 0xffffffffu);
                float4 q = sp[j];
                float dx = me.x - q.x;
                float dy = me.y - q.y;
                float dz = me.z - q.z;
                rp[kk] = frow;
                cp[kk] = (float)(base + j);
                wp[kk] = sqrtf(dx * dx + dy * dy + dz * dz);  // recomputed, as ref
                vp[kk] = 1.0f;
            } else {
                rp[kk] = 0.0f; cp[kk] = 0.0f; wp[kk] = 0.0f; vp[kk] = 0.0f;
            }
        }
        ((float4*)orow)[k4] = r4;
        ((float4*)ocol)[k4] = c4;
        ((float4*)ow  )[k4] = w4;
        ((float4*)oval)[k4] = v4;
    }
}

extern "C" void kernel_launch(void* const* d_in, const int* in_sizes, int n_in,
                              void* d_out, int out_size)
{
    const float* pos = (const float*)d_in[0];
    // d_in[1] = batch (int32) -- layout is fixed B x N contiguous, unused.
    float* out = (float*)d_out;

    dim3 grid(BGRAPHS * CHUNKS);   // 256 blocks
    dense_radius_graph_kernel<<<grid, TPB>>>(pos, out);
}

// round 3
// speedup vs baseline: 2.6116x; 2.6116x over previous
#include <cuda_runtime.h>

// DenseRadiusGraph: B=16 graphs, N=2048 nodes, D=3, cutoff=10, K=32.
// Output (float32, concat, M = B*N*K = 1048576):
//   [0,M) row ids, [M,2M) col ids, [2M,3M) weights, [3M,4M) valid flags.
//
// R3: 4 sub-threads per node (each scans a 512-span), per-node shared
// candidate buffer merged with shared atomics. 512 blocks x 256 thr
// -> 4096 warps (~28/SM, single wave) vs 1024 before.

#define BGRAPHS 16
#define NNODES  2048
#define KNBR    32
#define TPB     256
#define NODESB  64                    // nodes per block
#define QUART   4                     // sub-threads per node
#define SPAN    (NNODES / QUART)      // 512 j's per sub-thread
#define CAPS    40                    // shared candidate slots per node
#define CHUNKS  (NNODES / NODESB)     // 32 -> grid = 512 blocks

#define SMEM_BYTES (NNODES * 16 + NODESB * CAPS * 8 + NODESB * 4)

extern __shared__ unsigned char smem_raw[];

__global__ __launch_bounds__(TPB) void dense_radius_graph_kernel(
    const float* __restrict__ pos, float* __restrict__ out)
{
    float4* sp = (float4*)smem_raw;                                  // [2048] xyz + |p|^2
    unsigned long long* scand =
        (unsigned long long*)(smem_raw + NNODES * 16);               // [NODESB*CAPS]
    int* scnt = (int*)(smem_raw + NNODES * 16 + NODESB * CAPS * 8);  // [NODESB]

    const int b     = blockIdx.x / CHUNKS;     // graph
    const int chunk = blockIdx.x % CHUNKS;
    const int tid   = threadIdx.x;
    const int n     = tid & (NODESB - 1);      // local node   (lane-varying)
    const int q     = tid >> 6;                // quarter      (warp-uniform)

    if (tid < NODESB) scnt[tid] = 0;

    // Stage graph positions into shared with |p|^2 in .w
    const float* gp = pos + (size_t)b * NNODES * 3;
    for (int j = tid; j < NNODES; j += TPB) {
        float x = gp[3 * j + 0];
        float y = gp[3 * j + 1];
        float z = gp[3 * j + 2];
        sp[j] = make_float4(x, y, z, x * x + y * y + z * z);
    }
    __syncthreads();

    const int i = chunk * NODESB + n;          // node index within graph
    const float4 me = sp[i];

    // ---- scan this quarter's j-span; all lanes share j -> LDS broadcast ----
    const int j0 = q * SPAN;
    #pragma unroll 4
    for (int jj = 0; jj < SPAN; jj++) {
        const int j = j0 + jj;
        const float4 p = sp[j];
        const float s   = me.w + p.w;
        const float dot = me.x * p.x + me.y * p.y + me.z * p.z;
        const float d2  = s - 2.0f * dot;      // reference GEMM formulation
        if (d2 <= 100.001f) {                  // rare (~0.4% of lane-iters)
            const float dist = sqrtf(fmaxf(d2, 0.0f));
            if (j != i && dist <= 10.0f) {     // exact reference mask
                int idx = atomicAdd(&scnt[n], 1);
                if (idx < CAPS)
                    // dist>=0 -> bit order == float order; low bits = j for
                    // stable lower-index tie-break (matches lax.top_k).
                    scand[n * CAPS + idx] =
                        ((unsigned long long)__float_as_uint(dist) << 32) |
                        (unsigned int)j;
            }
        }
    }
    __syncthreads();

    // ---- per-node sort (ascending dist, then index); cnt ~ 8.6 avg ----
    if (tid < NODESB) {
        const int cnt = min(scnt[tid], CAPS);
        unsigned long long* c = scand + tid * CAPS;
        for (int a = 1; a < cnt; a++) {
            unsigned long long v = c[a];
            int x = a - 1;
            while (x >= 0 && c[x] > v) { c[x + 1] = c[x]; x--; }
            c[x + 1] = v;
        }
    }
    __syncthreads();

    // ---- output: thread (n,q) writes k in [q*8, q*8+8) ----
    const size_t M = (size_t)BGRAPHS * NNODES * KNBR;
    const size_t g = (size_t)b * NNODES + i;   // global node id
    const int m    = min(min(scnt[n], CAPS), KNBR);
    const unsigned long long* c = scand + n * CAPS;
    const float frow = (float)g;
    const int   base = b * NNODES;

    float* __restrict__ orow = out + g * KNBR + q * 8;
    float* __restrict__ ocol = out + M + g * KNBR + q * 8;
    float* __restrict__ ow   = out + 2 * M + g * KNBR + q * 8;
    float* __restrict__ oval = out + 3 * M + g * KNBR + q * 8;

    #pragma unroll
    for (int k4 = 0; k4 < 2; k4++) {
        float4 r4, c4, w4, v4;
        float* rp = (float*)&r4;
        float* cp = (float*)&c4;
        float* wp = (float*)&w4;
        float* vp = (float*)&v4;
        #pragma unroll
        for (int kk = 0; kk < 4; kk++) {
            const int k = q * 8 + k4 * 4 + kk;
            if (k < m) {
                const int j = (int)(c[k] & 0xffffffffu);
                const float4 p = sp[j];
                const float dx = me.x - p.x;
                const float dy = me.y - p.y;
                const float dz = me.z - p.z;
                rp[kk] = frow;
                cp[kk] = (float)(base + j);
                wp[kk] = sqrtf(dx * dx + dy * dy + dz * dz);  // recomputed, as ref
                vp[kk] = 1.0f;
            } else {
                rp[kk] = 0.0f; cp[kk] = 0.0f; wp[kk] = 0.0f; vp[kk] = 0.0f;
            }
        }
        ((float4*)orow)[k4] = r4;
        ((float4*)ocol)[k4] = c4;
        ((float4*)ow  )[k4] = w4;
        ((float4*)oval)[k4] = v4;
    }
}

extern "C" void kernel_launch(void* const* d_in, const int* in_sizes, int n_in,
                              void* d_out, int out_size)
{
    const float* pos = (const float*)d_in[0];
    float* out = (float*)d_out;

    static bool attr_set = false;
    if (!attr_set) {
        cudaFuncSetAttribute(dense_radius_graph_kernel,
                             cudaFuncAttributeMaxDynamicSharedMemorySize,
                             SMEM_BYTES);
        attr_set = true;
    }

    dim3 grid(BGRAPHS * CHUNKS);   // 512 blocks, single resident wave
    dense_radius_graph_kernel<<<grid, TPB, SMEM_BYTES>>>(pos, out);
}

// round 4
// speedup vs baseline: 2.6972x; 1.0328x over previous
#include <cuda_runtime.h>

// DenseRadiusGraph: B=16 graphs, N=2048 nodes, D=3, cutoff=10, K=32.
// Output (float32, concat, M = B*N*K = 1048576):
//   [0,M) row ids, [M,2M) col ids, [2M,3M) weights, [3M,4M) valid flags.
//
// R4: 8 sub-threads/node, grid 1024x256 (8192 warps, ~40/SM resident),
// 3-FFMA prefilter (0.5|p|^2 folded into the fma chain), exact reference
// d2 recomputed only in the rare (<0.5%) pass-path.

#define BGRAPHS 16
#define NNODES  2048
#define KNBR    32
#define TPB     256
#define NODESB  32                    // nodes per block
#define QUART   8                     // sub-threads per node
#define SPAN    (NNODES / QUART)      // 256 j's per sub-thread
#define CAPS    40                    // shared candidate slots per node
#define CHUNKS  (NNODES / NODESB)     // 64 -> grid = 1024 blocks

#define SMEM_BYTES (NNODES * 16 + NODESB * CAPS * 8 + NODESB * 4)

extern __shared__ unsigned char smem_raw[];

__global__ __launch_bounds__(TPB, 5) void dense_radius_graph_kernel(
    const float* __restrict__ pos, float* __restrict__ out)
{
    float4* sp = (float4*)smem_raw;                                  // [2048] xyz + 0.5|p|^2
    unsigned long long* scand =
        (unsigned long long*)(smem_raw + NNODES * 16);               // [NODESB*CAPS]
    int* scnt = (int*)(smem_raw + NNODES * 16 + NODESB * CAPS * 8);  // [NODESB]

    const int b     = blockIdx.x / CHUNKS;     // graph
    const int chunk = blockIdx.x % CHUNKS;
    const int tid   = threadIdx.x;
    const int n     = tid & (NODESB - 1);      // local node   (== lane id)
    const int q     = tid >> 5;                // eighth       (== warp id, uniform)

    if (tid < NODESB) scnt[tid] = 0;

    // Stage graph positions into shared with 0.5*|p|^2 in .w (exactly halved)
    const float* gp = pos + (size_t)b * NNODES * 3;
    for (int j = tid; j < NNODES; j += TPB) {
        float x = gp[3 * j + 0];
        float y = gp[3 * j + 1];
        float z = gp[3 * j + 2];
        sp[j] = make_float4(x, y, z, 0.5f * (x * x + y * y + z * z));
    }
    __syncthreads();

    const int i = chunk * NODESB + n;          // node index within graph
    const float4 me = sp[i];
    const float mew = 2.0f * me.w;             // exact |me|^2 (x2 is exact)
    // prefilter threshold: acc >= thr  <=>  d2_approx <= 100.06 (superset of
    // exact d2 <= 100.00001 given ~0.01 fma-chain rounding slop at |p|^2~3e4)
    const float thr = me.w - 50.03f;           // 0.5*|me|^2 - 50.03

    // ---- scan this eighth's j-span; all lanes share j -> LDS broadcast ----
    const int j0 = q * SPAN;
    #pragma unroll 4
    for (int jj = 0; jj < SPAN; jj++) {
        const int j = j0 + jj;
        const float4 p = sp[j];
        // acc = dot(me,p) - 0.5*|p|^2   (3 FFMAs)
        const float acc = fmaf(me.x, p.x, fmaf(me.y, p.y, fmaf(me.z, p.z, -p.w)));
        if (acc >= thr) {                      // rare (~0.4% of lane-iters)
            // exact reference formulation (identical to R3 bit-for-bit):
            const float pw  = 2.0f * p.w;                       // exact
            const float dot = me.x * p.x + me.y * p.y + me.z * p.z;
            const float d2  = (mew + pw) - 2.0f * dot;
            const float dist = sqrtf(fmaxf(d2, 0.0f));
            if (j != i && dist <= 10.0f) {
                int idx = atomicAdd(&scnt[n], 1);
                if (idx < CAPS)
                    // dist>=0 -> bit order == float order; low bits = j for
                    // stable lower-index tie-break (matches lax.top_k).
                    scand[n * CAPS + idx] =
                        ((unsigned long long)__float_as_uint(dist) << 32) |
                        (unsigned int)j;
            }
        }
    }
    __syncthreads();

    // ---- per-node sort (ascending dist, then index); cnt ~ 8.6 avg ----
    if (tid < NODESB) {
        const int cnt = min(scnt[tid], CAPS);
        unsigned long long* c = scand + tid * CAPS;
        for (int a = 1; a < cnt; a++) {
            unsigned long long v = c[a];
            int x = a - 1;
            while (x >= 0 && c[x] > v) { c[x + 1] = c[x]; x--; }
            c[x + 1] = v;
        }
    }
    __syncthreads();

    // ---- output: thread (n,q) writes k in [q*4, q*4+4) ----
    const size_t M = (size_t)BGRAPHS * NNODES * KNBR;
    const size_t g = (size_t)b * NNODES + i;   // global node id
    const int m    = min(min(scnt[n], CAPS), KNBR);
    const unsigned long long* c = scand + n * CAPS;
    const float frow = (float)g;
    const int   base = b * NNODES;

    float4 r4, c4, w4, v4;
    float* rp = (float*)&r4;
    float* cp = (float*)&c4;
    float* wp = (float*)&w4;
    float* vp = (float*)&v4;
    #pragma unroll
    for (int kk = 0; kk < 4; kk++) {
        const int k = q * 4 + kk;
        if (k < m) {
            const int j = (int)(c[k] & 0xffffffffu);
            const float4 p = sp[j];
            const float dx = me.x - p.x;
            const float dy = me.y - p.y;
            const float dz = me.z - p.z;
            rp[kk] = frow;
            cp[kk] = (float)(base + j);
            wp[kk] = sqrtf(dx * dx + dy * dy + dz * dz);  // recomputed, as ref
            vp[kk] = 1.0f;
        } else {
            rp[kk] = 0.0f; cp[kk] = 0.0f; wp[kk] = 0.0f; vp[kk] = 0.0f;
        }
    }
    ((float4*)(out + g * KNBR))[q]         = r4;
    ((float4*)(out + M + g * KNBR))[q]     = c4;
    ((float4*)(out + 2 * M + g * KNBR))[q] = w4;
    ((float4*)(out + 3 * M + g * KNBR))[q] = v4;
}

extern "C" void kernel_launch(void* const* d_in, const int* in_sizes, int n_in,
                              void* d_out, int out_size)
{
    const float* pos = (const float*)d_in[0];
    float* out = (float*)d_out;

    static bool attr_set = false;
    if (!attr_set) {
        cudaFuncSetAttribute(dense_radius_graph_kernel,
                             cudaFuncAttributeMaxDynamicSharedMemorySize,
                             SMEM_BYTES);
        attr_set = true;
    }

    dim3 grid(BGRAPHS * CHUNKS);   // 1024 blocks
    dense_radius_graph_kernel<<<grid, TPB, SMEM_BYTES>>>(pos, out);
}

// round 5
// speedup vs baseline: 2.8688x; 1.0636x over previous
#include <cuda_runtime.h>

// DenseRadiusGraph: B=16 graphs, N=2048 nodes, D=3, cutoff=10, K=32.
// Output (float32, concat, M = B*N*K = 1048576):
//   [0,M) row ids, [M,2M) col ids, [2M,3M) weights, [3M,4M) valid flags.
//
// R5: positions moved from per-block smem tile (32KB, caused 2-wave launch
// with 38%-full tail wave) to a packed __device__ float4 array scanned via
// LDG.128 broadcast (L1-resident). smem now 10.4KB -> 7 blocks/SM -> the
// whole 1024-block grid runs as ONE wave.

#define BGRAPHS 16
#define NNODES  2048
#define KNBR    32
#define TPB     256
#define NODESB  32                    // nodes per block
#define QUART   8                    // sub-threads per node (== warps/block)
#define SPAN    (NNODES / QUART)      // 256 j's per sub-thread
#define CAPS    40                    // candidate slots per node
#define CHUNKS  (NNODES / NODESB)     // 64 -> grid = 1024 blocks
#define NTOT    (BGRAPHS * NNODES)

// packed positions: x, y, z, 0.5*|p|^2   (512 KB device global scratch)
__device__ float4 g_packed[NTOT];

__global__ void pack_kernel(const float* __restrict__ pos)
{
    const int t = blockIdx.x * blockDim.x + threadIdx.x;
    if (t < NTOT) {
        const float x = pos[3 * t + 0];
        const float y = pos[3 * t + 1];
        const float z = pos[3 * t + 2];
        g_packed[t] = make_float4(x, y, z, 0.5f * (x * x + y * y + z * z));
    }
}

__global__ __launch_bounds__(TPB, 7) void scan_kernel(float* __restrict__ out)
{
    __shared__ unsigned long long scand[NODESB * CAPS];
    __shared__ int scnt[NODESB];

    const int b     = blockIdx.x / CHUNKS;     // graph
    const int chunk = blockIdx.x % CHUNKS;
    const int tid   = threadIdx.x;
    const int n     = tid & (NODESB - 1);      // local node (== lane id)
    const int q     = tid >> 5;                // eighth     (== warp id)

    if (tid < NODESB) scnt[tid] = 0;
    __syncthreads();

    const float4* __restrict__ gp = g_packed + b * NNODES;

    const int i = chunk * NODESB + n;          // node index within graph
    const float4 me = __ldg(&gp[i]);
    const float mew = 2.0f * me.w;             // exact |me|^2 (x2 exact)
    // prefilter: acc >= thr  <=>  d2_approx <= 100.06 (superset of exact
    // d2 <= 100.00001 given ~0.01 fma-chain rounding slop at |p|^2 ~ 3e4)
    const float thr = me.w - 50.03f;

    // ---- scan this eighth's span; all lanes share j -> 1 line per LDG ----
    const int j0 = q * SPAN;
    #pragma unroll 8
    for (int jj = 0; jj < SPAN; jj++) {
        const int j = j0 + jj;
        const float4 p = __ldg(&gp[j]);
        // acc = dot(me,p) - 0.5*|p|^2   (3 FFMAs, negate folded into FFMA)
        const float acc = fmaf(me.x, p.x, fmaf(me.y, p.y, fmaf(me.z, p.z, -p.w)));
        if (acc >= thr) {                      // rare (~0.4% of lane-iters)
            // exact reference formulation (bit-identical to R3/R4):
            const float pw  = 2.0f * p.w;
            const float dot = me.x * p.x + me.y * p.y + me.z * p.z;
            const float d2  = (mew + pw) - 2.0f * dot;
            const float dist = sqrtf(fmaxf(d2, 0.0f));
            if (j != i && dist <= 10.0f) {
                int idx = atomicAdd(&scnt[n], 1);
                if (idx < CAPS)
                    // dist>=0 -> bit order == float order; low bits = j ->
                    // stable lower-index tie-break (matches lax.top_k).
                    scand[n * CAPS + idx] =
                        ((unsigned long long)__float_as_uint(dist) << 32) |
                        (unsigned int)j;
            }
        }
    }
    __syncthreads();

    // ---- per-node sort (ascending dist, then index); cnt ~ 8.6 avg ----
    if (tid < NODESB) {
        const int cnt = min(scnt[tid], CAPS);
        unsigned long long* c = scand + tid * CAPS;
        for (int a = 1; a < cnt; a++) {
            unsigned long long v = c[a];
            int x = a - 1;
            while (x >= 0 && c[x] > v) { c[x + 1] = c[x]; x--; }
            c[x + 1] = v;
        }
    }
    __syncthreads();

    // ---- output: thread (n,q) writes k in [q*4, q*4+4) ----
    const size_t M = (size_t)BGRAPHS * NNODES * KNBR;
    const size_t g = (size_t)b * NNODES + i;   // global node id
    const int m    = min(min(scnt[n], CAPS), KNBR);
    const unsigned long long* c = scand + n * CAPS;
    const float frow = (float)g;
    const int   base = b * NNODES;

    float4 r4, c4, w4, v4;
    float* rp = (float*)&r4;
    float* cp = (float*)&c4;
    float* wp = (float*)&w4;
    float* vp = (float*)&v4;
    #pragma unroll
    for (int kk = 0; kk < 4; kk++) {
        const int k = q * 4 + kk;
        if (k < m) {
            const int j = (int)(c[k] & 0xffffffffu);
            const float4 p = __ldg(&gp[j]);
            const float dx = me.x - p.x;
            const float dy = me.y - p.y;
            const float dz = me.z - p.z;
            rp[kk] = frow;
            cp[kk] = (float)(base + j);
            wp[kk] = sqrtf(dx * dx + dy * dy + dz * dz);  // recomputed, as ref
            vp[kk] = 1.0f;
        } else {
            rp[kk] = 0.0f; cp[kk] = 0.0f; wp[kk] = 0.0f; vp[kk] = 0.0f;
        }
    }
    ((float4*)(out + g * KNBR))[q]         = r4;
    ((float4*)(out + M + g * KNBR))[q]     = c4;
    ((float4*)(out + 2 * M + g * KNBR))[q] = w4;
    ((float4*)(out + 3 * M + g * KNBR))[q] = v4;
}

extern "C" void kernel_launch(void* const* d_in, const int* in_sizes, int n_in,
                              void* d_out, int out_size)
{
    const float* pos = (const float*)d_in[0];
    float* out = (float*)d_out;

    pack_kernel<<<(NTOT + TPB - 1) / TPB, TPB>>>(pos);
    scan_kernel<<<BGRAPHS * CHUNKS, TPB>>>(out);   // 1024 blocks, single wave
}